// round 10
// baseline (speedup 1.0000x reference)
#include <cuda_runtime.h>
#include <math.h>
#include <stdint.h>

// Problem constants
#define NB   16          // batch
#define NC   256         // channels
#define NHW  1024        // H*W
#define NG   32          // groups
#define CHW  (NC*NHW)    // 262144 per-batch activation size
#define KC   (9*NC)      // 2304 conv GEMM depth

// ---------------- scratch (device globals; no runtime allocation) ----------
__device__ float g_t0[NB*CHW];
__device__ float g_t1[NB*CHW];
__device__ float g_t2[NB*CHW];
__device__ float g_h [NB*CHW];
__device__ float g_qkv[NB*3*CHW];         // 50 MB
__device__ float g_att[(long)NB*NHW*NHW]; // 67 MB
__device__ float g_film[NB*NC];
__device__ float g_mean[NB*NG];
__device__ float g_rstd[NB*NG];
__device__ float g_pw1[NC*KC];            // permuted+tf32 conv1 weights
__device__ float g_pw2[NC*KC];            // permuted+tf32 conv2 weights
__device__ float g_wq[3*NC*NC];           // tf32 qkv weights
__device__ float g_wr[NC*NC];             // tf32 res weights
__device__ float g_wo[NC*NC];             // tf32 out weights
__device__ float g_xc[NB*CHW];            // tf32 copy of x

// ---------------- TF32 helpers ----------------------------------------------
__device__ __forceinline__ uint32_t to_tf32(float x) {
    uint32_t y;
    asm("cvt.rna.tf32.f32 %0, %1;" : "=r"(y) : "f"(x));
    return y;
}
__device__ __forceinline__ float to_tf32f(float x) {
    return __uint_as_float(to_tf32(x));
}

// ---------------- cp.async / ldmatrix helpers --------------------------------
__device__ __forceinline__ void cp16(uint32_t dst, const float* src) {
    asm volatile("cp.async.cg.shared.global [%0], [%1], 16;\n"
                 :: "r"(dst), "l"(src));
}
__device__ __forceinline__ void cp4z(uint32_t dst, const float* src, int sz) {
    asm volatile("cp.async.ca.shared.global [%0], [%1], 4, %2;\n"
                 :: "r"(dst), "l"(src), "r"(sz));
}
__device__ __forceinline__ void cp_commit() {
    asm volatile("cp.async.commit_group;\n");
}
__device__ __forceinline__ void cp_wait1() {
    asm volatile("cp.async.wait_group 1;\n");
}
__device__ __forceinline__ void ldsm_x4(uint32_t& r0, uint32_t& r1,
                                        uint32_t& r2, uint32_t& r3, uint32_t a) {
    asm volatile("ldmatrix.sync.aligned.m8n8.x4.shared.b16 {%0,%1,%2,%3}, [%4];"
                 : "=r"(r0), "=r"(r1), "=r"(r2), "=r"(r3) : "r"(a));
}
__device__ __forceinline__ void ldsm_x2(uint32_t& r0, uint32_t& r1, uint32_t a) {
    asm volatile("ldmatrix.sync.aligned.m8n8.x2.shared.b16 {%0,%1}, [%2];"
                 : "=r"(r0), "=r"(r1) : "r"(a));
}

// ---------------- weight permute+convert: pw[m][r*256+ci] = w[m][ci*9+r] ----
__global__ void permw_kernel(const float* __restrict__ w, float* __restrict__ pw) {
    int idx = blockIdx.x * 256 + threadIdx.x;   // covers 256*2304
    int m = idx / KC;
    int k = idx - m*KC;
    int r = k >> 8;
    int ci = k & 255;
    pw[idx] = to_tf32f(w[m*KC + ci*9 + r]);
}

// ---------------- elementwise tf32 convert ----------------------------------
__global__ void cvt_kernel(const float* __restrict__ in, float* __restrict__ out) {
    long idx = (long)blockIdx.x * 256 + threadIdx.x;
    out[idx] = to_tf32f(in[idx]);
}

// ---------------- FiLM: film[b][co] = emb[b] @ noise_w + noise_b -----------
__global__ void film_kernel(const float* __restrict__ emb,
                            const float* __restrict__ w,
                            const float* __restrict__ nb,
                            float* __restrict__ film) {
    int b = blockIdx.x;
    int co = threadIdx.x;
    __shared__ float e[NC];
    e[co] = emb[b*NC + co];
    __syncthreads();
    float acc = nb[co];
    #pragma unroll 8
    for (int k = 0; k < NC; k++) acc += e[k] * w[k*NC + co];
    film[b*NC + co] = acc;
}

// ---------------- GroupNorm stats ------------------------------------------
__global__ void gn_stats_kernel(const float* __restrict__ x,
                                float* __restrict__ mean,
                                float* __restrict__ rstd) {
    int bg = blockIdx.x;                      // 0..511
    const float* p = x + (long)bg * 8192;
    int t = threadIdx.x;
    float s = 0.f, s2 = 0.f;
    for (int i = t; i < 8192; i += 256) {
        float v = p[i];
        s += v; s2 += v*v;
    }
    __shared__ float sh[256], sh2[256];
    sh[t] = s; sh2[t] = s2;
    __syncthreads();
    for (int o = 128; o > 0; o >>= 1) {
        if (t < o) { sh[t] += sh[t+o]; sh2[t] += sh2[t+o]; }
        __syncthreads();
    }
    if (t == 0) {
        float m = sh[0] * (1.f/8192.f);
        float var = sh2[0] * (1.f/8192.f) - m*m;
        mean[bg] = m;
        rstd[bg] = rsqrtf(var + 1e-5f);
    }
}

// ---------------- GroupNorm apply (+optional SiLU), tf32-rounded output -----
__global__ void gn_apply_kernel(const float* __restrict__ x,
                                const float* __restrict__ mean,
                                const float* __restrict__ rstd,
                                const float* __restrict__ scale,
                                const float* __restrict__ bias,
                                float* __restrict__ y,
                                int do_silu) {
    long idx = (long)blockIdx.x * 256 + threadIdx.x;
    int b   = (int)(idx >> 18);
    int ofs = (int)(idx & (CHW-1));
    int g   = ofs >> 13;
    int c   = ofs >> 10;
    int bg  = b*NG + g;
    float v = (x[idx] - mean[bg]) * rstd[bg] * scale[c] + bias[c];
    if (do_silu) v = v / (1.f + expf(-v));
    y[idx] = to_tf32f(v);
}

// ---------------- Softmax over rows of 1024, tf32-rounded output ------------
__global__ void softmax_kernel(float* __restrict__ S) {
    long row = blockIdx.x;
    float* p = S + row * NHW;
    int t = threadIdx.x;
    float v[4];
    float mx = -1e30f;
    #pragma unroll
    for (int j = 0; j < 4; j++) { v[j] = p[t + j*256]; mx = fmaxf(mx, v[j]); }
    __shared__ float sh[256];
    sh[t] = mx; __syncthreads();
    for (int o = 128; o > 0; o >>= 1) { if (t < o) sh[t] = fmaxf(sh[t], sh[t+o]); __syncthreads(); }
    mx = sh[0]; __syncthreads();
    float s = 0.f;
    #pragma unroll
    for (int j = 0; j < 4; j++) { v[j] = expf(v[j] - mx); s += v[j]; }
    sh[t] = s; __syncthreads();
    for (int o = 128; o > 0; o >>= 1) { if (t < o) sh[t] += sh[t+o]; __syncthreads(); }
    float inv = 1.f / sh[0];
    #pragma unroll
    for (int j = 0; j < 4; j++) p[t + j*256] = to_tf32f(v[j] * inv);
}

__device__ __forceinline__ void mma_tf32(float c[4], uint32_t a0, uint32_t a1,
                                         uint32_t a2, uint32_t a3,
                                         uint32_t b0, uint32_t b1) {
    asm volatile(
        "mma.sync.aligned.m16n8k8.row.col.f32.tf32.tf32.f32 "
        "{%0,%1,%2,%3}, {%4,%5,%6,%7}, {%8,%9}, {%0,%1,%2,%3};\n"
        : "+f"(c[0]), "+f"(c[1]), "+f"(c[2]), "+f"(c[3])
        : "r"(a0), "r"(a1), "r"(a2), "r"(a3), "r"(b0), "r"(b1));
}

// ---------------- Batched 256x128x16 TF32 GEMM, 3-stage cp.async ------------
// All inputs PRE-ROUNDED tf32 bits; 8 warps as 4m x 2n, 64x64 warp tiles.
// A fragments via ldmatrix when TA==0; B fragments via ldmatrix when TB==1.
// TA=0: A row-major [M][K], smem [m][k] stride 20
// TA=1: A is [K][M],        smem [k][m] stride 264
// TB=0: B is [K][N],        smem [k][n] stride 136
// TB=1: B is [N][K],        smem [n][k] stride 20
// IMC : B image [Ci][32][32], K=9*Ci with k=r*256+ci (tap-major); [k][n] 136.
#define SA0 20
#define SAM 264
#define SKN 136
#define SNK 20
#define ASZ 5120            // max(256*20, 16*264)
#define BSZ 2560            // max(16*136, 128*20)
#define STG (ASZ+BSZ)       // floats per stage
#define GEMM_SMEM (3*STG*4) // 92160 bytes

template<int TA, int TB, bool IMC, int RND>
__global__ __launch_bounds__(256)
void gemm_tc_kernel(const float* __restrict__ A,
                    const float* __restrict__ Bp,
                    float* __restrict__ Cp,
                    int M, int N, int K,
                    long sA, long sB, long sC,
                    float alpha,
                    const float* __restrict__ bias,
                    const float* __restrict__ film,
                    const float* __restrict__ addsrc,
                    int accumulate) {
    extern __shared__ __align__(16) float smem[];

    int b  = blockIdx.z;
    const float* Ab = A  + (long)b * sA;
    const float* Bb = Bp + (long)b * sB;
    float*       Cb = Cp + (long)b * sC;
    int m0 = blockIdx.y * 256;
    int n0 = blockIdx.x * 128;
    int t    = threadIdx.x;
    int lane = t & 31;
    int wid  = t >> 5;
    int wm   = wid >> 1;         // warp m index (0..3) -> 64 rows
    int wn   = wid & 1;          // warp n index (0..1) -> 64 cols
    int grp  = lane >> 2;        // 0..7
    int qd   = lane & 3;         // 0..3
    // ldmatrix per-lane row/col selectors
    int lmA_r = lane & 15;               // row offset within 16-row block
    int lmA_c = ((lane >> 4) & 1) << 2;  // col +0 / +4
    int lmB_r = lane & 7;                // row offset within 8-row block
    int lmB_c = ((lane >> 3) & 1) << 2;  // col +0 / +4 (x2: lanes 0-15)

    uint32_t sb = (uint32_t)__cvta_generic_to_shared(&smem[0]);

    float acc[4][8][4];
    #pragma unroll
    for (int i = 0; i < 4; i++)
        #pragma unroll
        for (int j = 0; j < 8; j++)
            #pragma unroll
            for (int r = 0; r < 4; r++) acc[i][j][r] = 0.f;

    // im2col per-thread constants
    int ic_n  = t & 127;
    int ic_kr = t >> 7;                    // 0..1
    int ic_h  = (n0 + ic_n) >> 5;
    int ic_w  = (n0 + ic_n) & 31;

    auto prefA = [&](int kk, int s) {
        uint32_t ab = sb + (uint32_t)(s*STG)*4u;
        if (TA == 0) {
            #pragma unroll
            for (int r = 0; r < 4; r++) {       // 256x16 = 1024 float4
                int c = t + r*256;
                int m = c >> 2;
                int kq = (c & 3) << 2;
                cp16(ab + (uint32_t)(m*SA0 + kq)*4u,
                     Ab + (long)(m0+m)*K + kk + kq);
            }
        } else {
            #pragma unroll
            for (int r = 0; r < 4; r++) {       // 16x256 = 1024 float4
                int c = t + r*256;
                int k = c >> 6;
                int mq = (c & 63) << 2;
                cp16(ab + (uint32_t)(k*SAM + mq)*4u,
                     Ab + (long)(kk+k)*M + m0 + mq);
            }
        }
    };
    auto prefB = [&](int kk, int s) {
        uint32_t bbase = sb + (uint32_t)(s*STG + ASZ)*4u;
        if (IMC) {
            int r   = kk >> 8;            // constant tap for this tile
            int ci0 = (kk & 255) + ic_kr*8;
            int kh  = r / 3, kw = r - kh*3;
            int ih  = ic_h + kh - 1, iw = ic_w + kw - 1;
            bool ok = (ih >= 0 && ih < 32 && iw >= 0 && iw < 32);
            const float* src = ok ? (Bb + (long)ci0*NHW + ih*32 + iw) : Bb;
            int sz = ok ? 4 : 0;
            #pragma unroll
            for (int j = 0; j < 8; j++)
                cp4z(bbase + (uint32_t)((ic_kr*8 + j)*SKN + ic_n)*4u,
                     src + j*NHW, sz);
        } else if (TB == 0) {
            #pragma unroll
            for (int r = 0; r < 2; r++) {       // 16x128 = 512 float4
                int c = t + r*256;
                int k = c >> 5;
                int nq = (c & 31) << 2;
                cp16(bbase + (uint32_t)(k*SKN + nq)*4u,
                     Bb + (long)(kk+k)*N + n0 + nq);
            }
        } else {
            #pragma unroll
            for (int r = 0; r < 2; r++) {       // 128x16 = 512 float4
                int c = t + r*256;
                int n = c >> 2;
                int kq = (c & 3) << 2;
                cp16(bbase + (uint32_t)(n*SNK + kq)*4u,
                     Bb + (long)(n0+n)*K + kk + kq);
            }
        }
    };
    auto compute = [&](int s) {
        const uint32_t* AsU = reinterpret_cast<const uint32_t*>(&smem[s*STG]);
        const uint32_t* BsU = reinterpret_cast<const uint32_t*>(&smem[s*STG + ASZ]);
        uint32_t abase = sb + (uint32_t)(s*STG)*4u;
        uint32_t bbase = sb + (uint32_t)(s*STG + ASZ)*4u;
        #pragma unroll
        for (int ks = 0; ks < 16; ks += 8) {
            uint32_t af[4][4];
            #pragma unroll
            for (int mt = 0; mt < 4; mt++) {
                if (TA == 0) {
                    uint32_t a = abase +
                        (uint32_t)((wm*64 + mt*16 + lmA_r)*SA0 + ks + lmA_c)*4u;
                    ldsm_x4(af[mt][0], af[mt][1], af[mt][2], af[mt][3], a);
                } else {
                    int mb = wm*64 + mt*16 + grp;
                    af[mt][0] = AsU[(ks+qd)*SAM + mb];
                    af[mt][1] = AsU[(ks+qd)*SAM + mb + 8];
                    af[mt][2] = AsU[(ks+4+qd)*SAM + mb];
                    af[mt][3] = AsU[(ks+4+qd)*SAM + mb + 8];
                }
            }
            uint32_t bf[8][2];
            #pragma unroll
            for (int nt = 0; nt < 8; nt++) {
                if (TB == 1) {
                    uint32_t a = bbase +
                        (uint32_t)((wn*64 + nt*8 + lmB_r)*SNK + ks + lmB_c)*4u;
                    ldsm_x2(bf[nt][0], bf[nt][1], a);
                } else {
                    int nb = wn*64 + nt*8 + grp;
                    bf[nt][0] = BsU[(ks+qd)*SKN + nb];
                    bf[nt][1] = BsU[(ks+4+qd)*SKN + nb];
                }
            }
            #pragma unroll
            for (int mt = 0; mt < 4; mt++)
                #pragma unroll
                for (int nt = 0; nt < 8; nt++)
                    mma_tf32(acc[mt][nt], af[mt][0], af[mt][1], af[mt][2], af[mt][3],
                             bf[nt][0], bf[nt][1]);
        }
    };

    // ---- 3-stage pipelined mainloop ----
    int T = K >> 4;
    prefA(0, 0); prefB(0, 0); cp_commit();
    prefA(16, 1); prefB(16, 1); cp_commit();
    for (int i = 0; i < T; i++) {
        cp_wait1();
        __syncthreads();
        if (i + 2 < T) {
            int s2 = (i + 2) % 3;
            prefA((i+2)*16, s2); prefB((i+2)*16, s2);
        }
        cp_commit();
        compute(i % 3);
        __syncthreads();
    }

    // ---- epilogue ----
    #pragma unroll
    for (int mt = 0; mt < 4; mt++) {
        int mr0 = m0 + wm*64 + mt*16 + grp;
        int mr1 = mr0 + 8;
        float badd0 = 0.f, badd1 = 0.f;
        if (bias) { badd0 += bias[mr0]; badd1 += bias[mr1]; }
        if (film) { badd0 += film[b*M + mr0]; badd1 += film[b*M + mr1]; }
        #pragma unroll
        for (int nt = 0; nt < 8; nt++) {
            int nc = n0 + wn*64 + nt*8 + qd*2;
            long i0 = (long)mr0 * N + nc;
            long i1 = (long)mr1 * N + nc;
            float v00 = acc[mt][nt][0] * alpha + badd0;
            float v01 = acc[mt][nt][1] * alpha + badd0;
            float v10 = acc[mt][nt][2] * alpha + badd1;
            float v11 = acc[mt][nt][3] * alpha + badd1;
            if (addsrc) {
                v00 += addsrc[(long)b*sC + i0];
                v01 += addsrc[(long)b*sC + i0 + 1];
                v10 += addsrc[(long)b*sC + i1];
                v11 += addsrc[(long)b*sC + i1 + 1];
            }
            if (accumulate) {
                v00 += Cb[i0]; v01 += Cb[i0 + 1];
                v10 += Cb[i1]; v11 += Cb[i1 + 1];
            }
            if (RND) {
                v00 = to_tf32f(v00); v01 = to_tf32f(v01);
                v10 = to_tf32f(v10); v11 = to_tf32f(v11);
            }
            *reinterpret_cast<float2*>(&Cb[i0]) = make_float2(v00, v01);
            *reinterpret_cast<float2*>(&Cb[i1]) = make_float2(v10, v11);
        }
    }
}

// ---------------- host launch ------------------------------------------------
extern "C" void kernel_launch(void* const* d_in, const int* in_sizes, int n_in,
                              void* d_out, int out_size) {
    const float* x          = (const float*)d_in[0];
    const float* noise_emb  = (const float*)d_in[1];
    const float* gn1_scale  = (const float*)d_in[2];
    const float* gn1_bias   = (const float*)d_in[3];
    const float* conv1_w    = (const float*)d_in[4];
    const float* conv1_b    = (const float*)d_in[5];
    const float* noise_w    = (const float*)d_in[6];
    const float* noise_b    = (const float*)d_in[7];
    const float* gn2_scale  = (const float*)d_in[8];
    const float* gn2_bias   = (const float*)d_in[9];
    const float* conv2_w    = (const float*)d_in[10];
    const float* conv2_b    = (const float*)d_in[11];
    const float* res_w      = (const float*)d_in[12];
    const float* res_b      = (const float*)d_in[13];
    const float* agn_scale  = (const float*)d_in[14];
    const float* agn_bias   = (const float*)d_in[15];
    const float* qkv_w      = (const float*)d_in[16];
    const float* out_w      = (const float*)d_in[17];
    const float* out_b      = (const float*)d_in[18];
    float* out = (float*)d_out;

    float *t0, *t1, *t2, *h, *qkv, *att, *film, *mean, *rstd;
    float *pw1, *pw2, *wq, *wr, *wo, *xc;
    cudaGetSymbolAddress((void**)&t0,   g_t0);
    cudaGetSymbolAddress((void**)&t1,   g_t1);
    cudaGetSymbolAddress((void**)&t2,   g_t2);
    cudaGetSymbolAddress((void**)&h,    g_h);
    cudaGetSymbolAddress((void**)&qkv,  g_qkv);
    cudaGetSymbolAddress((void**)&att,  g_att);
    cudaGetSymbolAddress((void**)&film, g_film);
    cudaGetSymbolAddress((void**)&mean, g_mean);
    cudaGetSymbolAddress((void**)&rstd, g_rstd);
    cudaGetSymbolAddress((void**)&pw1,  g_pw1);
    cudaGetSymbolAddress((void**)&pw2,  g_pw2);
    cudaGetSymbolAddress((void**)&wq,   g_wq);
    cudaGetSymbolAddress((void**)&wr,   g_wr);
    cudaGetSymbolAddress((void**)&wo,   g_wo);
    cudaGetSymbolAddress((void**)&xc,   g_xc);

    cudaFuncSetAttribute(gemm_tc_kernel<0,0,true,0>,
        cudaFuncAttributeMaxDynamicSharedMemorySize, GEMM_SMEM);
    cudaFuncSetAttribute(gemm_tc_kernel<0,0,false,0>,
        cudaFuncAttributeMaxDynamicSharedMemorySize, GEMM_SMEM);
    cudaFuncSetAttribute(gemm_tc_kernel<0,0,false,1>,
        cudaFuncAttributeMaxDynamicSharedMemorySize, GEMM_SMEM);
    cudaFuncSetAttribute(gemm_tc_kernel<1,0,false,0>,
        cudaFuncAttributeMaxDynamicSharedMemorySize, GEMM_SMEM);
    cudaFuncSetAttribute(gemm_tc_kernel<0,1,false,1>,
        cudaFuncAttributeMaxDynamicSharedMemorySize, GEMM_SMEM);

    const int ELTS = NB * CHW;            // 4194304
    const int EW_GRID = ELTS / 256;       // 16384
    const int PW_GRID = NC*KC/256;        // 2304

    // Launch order chosen so ncu (-s 5 -c 1) captures launch #6 = conv1 GEMM.
    film_kernel<<<NB, NC>>>(noise_emb, noise_w, noise_b, film);            // 1
    gn_stats_kernel<<<NB*NG, 256>>>(x, mean, rstd);                        // 2
    gn_apply_kernel<<<EW_GRID, 256>>>(x, mean, rstd, gn1_scale, gn1_bias,  // 3
                                      t0, 1);
    permw_kernel<<<PW_GRID, 256>>>(conv1_w, pw1);                          // 4
    permw_kernel<<<PW_GRID, 256>>>(conv2_w, pw2);                          // 5

    // conv1 (3x3, tap-major im2col GEMM) + FiLM add fused                 // 6
    gemm_tc_kernel<0,0,true,0><<<dim3(8,1,NB), 256, GEMM_SMEM>>>(
        pw1, t0, t1, NC, NHW, KC, 0, CHW, CHW, 1.f,
        conv1_b, film, nullptr, 0);

    // remaining one-shot conversions (needed before their consumers)
    cvt_kernel<<<3*NC*NC/256, 256>>>(qkv_w, wq);
    cvt_kernel<<<NC*NC/256, 256>>>(res_w, wr);
    cvt_kernel<<<NC*NC/256, 256>>>(out_w, wo);
    cvt_kernel<<<EW_GRID, 256>>>(x, xc);

    // GN2 + SiLU (tf32 out)
    gn_stats_kernel<<<NB*NG, 256>>>(t1, mean, rstd);
    gn_apply_kernel<<<EW_GRID, 256>>>(t1, mean, rstd, gn2_scale, gn2_bias, t2, 1);

    // residual 1x1 conv -> h (fp32 out)
    gemm_tc_kernel<0,0,false,0><<<dim3(8,1,NB), 256, GEMM_SMEM>>>(
        wr, xc, h, NC, NHW, NC, 0, CHW, CHW, 1.f,
        res_b, nullptr, nullptr, 0);

    // conv2 (3x3) accumulates into h (fp32)
    gemm_tc_kernel<0,0,true,0><<<dim3(8,1,NB), 256, GEMM_SMEM>>>(
        pw2, t2, h, NC, NHW, KC, 0, CHW, CHW, 1.f,
        conv2_b, nullptr, nullptr, 1);

    // attention GroupNorm (no SiLU, tf32 out) -> t0
    gn_stats_kernel<<<NB*NG, 256>>>(h, mean, rstd);
    gn_apply_kernel<<<EW_GRID, 256>>>(h, mean, rstd, agn_scale, agn_bias, t0, 0);

    // qkv 1x1 conv (no bias), output tf32-rounded
    gemm_tc_kernel<0,0,false,1><<<dim3(8,3,NB), 256, GEMM_SMEM>>>(
        wq, t0, qkv, 3*NC, NHW, NC, 0, CHW, (long)3*CHW, 1.f,
        nullptr, nullptr, nullptr, 0);

    // scores: S[b][s][t] = (1/16) * sum_d q[d][s] k[d][t]   (A is [K][M])
    gemm_tc_kernel<1,0,false,0><<<dim3(8,4,NB), 256, GEMM_SMEM>>>(
        qkv /*q*/, qkv + CHW /*k*/, att, NHW, NHW, NC,
        (long)3*CHW, (long)3*CHW, (long)NHW*NHW, 0.0625f,
        nullptr, nullptr, nullptr, 0);

    // softmax rows (tf32 out)
    softmax_kernel<<<NB*NHW, 256>>>(att);

    // AV: O[b][d][s] = sum_t v[d][t] S[s][t] (B is [N][K], ldmatrix)
    gemm_tc_kernel<0,1,false,1><<<dim3(8,1,NB), 256, GEMM_SMEM>>>(
        qkv + 2*CHW /*v*/, att, t2, NC, NHW, NHW,
        (long)3*CHW, (long)NHW*NHW, CHW, 1.f,
        nullptr, nullptr, nullptr, 0);

    // out 1x1 conv + bias + residual h -> d_out (fp32)
    gemm_tc_kernel<0,0,false,0><<<dim3(8,1,NB), 256, GEMM_SMEM>>>(
        wo, t2, out, NC, NHW, NC, 0, CHW, CHW, 1.f,
        out_b, nullptr, h, 0);
}

// round 12
// speedup vs baseline: 1.0466x; 1.0466x over previous
#include <cuda_runtime.h>
#include <math.h>
#include <stdint.h>

// Problem constants
#define NB   16          // batch
#define NC   256         // channels
#define NHW  1024        // H*W
#define NG   32          // groups
#define CHW  (NC*NHW)    // 262144 per-batch activation size
#define KC   (9*NC)      // 2304 conv GEMM depth

// ---------------- scratch (device globals; no runtime allocation) ----------
__device__ float g_t0[NB*CHW];
__device__ float g_t1[NB*CHW];
__device__ float g_t2[NB*CHW];
__device__ float g_h [NB*CHW];
__device__ float g_qkv[NB*3*CHW];         // 50 MB
__device__ float g_att[(long)NB*NHW*NHW]; // 67 MB
__device__ float g_film[NB*NC];
__device__ float g_pw1[NC*KC];            // permuted+tf32 conv1 weights
__device__ float g_pw2[NC*KC];            // permuted+tf32 conv2 weights
__device__ float g_wq[3*NC*NC];           // tf32 qkv weights
__device__ float g_wr[NC*NC];             // tf32 res weights
__device__ float g_wo[NC*NC];             // tf32 out weights
__device__ float g_xc[NB*CHW];            // tf32 copy of x

// ---------------- TF32 helpers ----------------------------------------------
__device__ __forceinline__ uint32_t to_tf32(float x) {
    uint32_t y;
    asm("cvt.rna.tf32.f32 %0, %1;" : "=r"(y) : "f"(x));
    return y;
}
__device__ __forceinline__ float to_tf32f(float x) {
    return __uint_as_float(to_tf32(x));
}

// ---------------- cp.async helpers ------------------------------------------
__device__ __forceinline__ void cp16(uint32_t dst, const float* src) {
    asm volatile("cp.async.cg.shared.global [%0], [%1], 16;\n"
                 :: "r"(dst), "l"(src));
}
__device__ __forceinline__ void cp4z(uint32_t dst, const float* src, int sz) {
    asm volatile("cp.async.ca.shared.global [%0], [%1], 4, %2;\n"
                 :: "r"(dst), "l"(src), "r"(sz));
}
__device__ __forceinline__ void cp_commit() {
    asm volatile("cp.async.commit_group;\n");
}
__device__ __forceinline__ void cp_wait1() {
    asm volatile("cp.async.wait_group 1;\n");
}

// ---------------- weight permute+convert: pw[m][r*256+ci] = w[m][ci*9+r] ----
__global__ void permw_kernel(const float* __restrict__ w, float* __restrict__ pw) {
    int idx = blockIdx.x * 256 + threadIdx.x;   // covers 256*2304
    int m = idx / KC;
    int k = idx - m*KC;
    int r = k >> 8;
    int ci = k & 255;
    pw[idx] = to_tf32f(w[m*KC + ci*9 + r]);
}

// ---------------- elementwise tf32 convert ----------------------------------
__global__ void cvt_kernel(const float* __restrict__ in, float* __restrict__ out) {
    long idx = (long)blockIdx.x * 256 + threadIdx.x;
    out[idx] = to_tf32f(in[idx]);
}

// ---------------- FiLM: film[b][co] = emb[b] @ noise_w + noise_b -----------
__global__ void film_kernel(const float* __restrict__ emb,
                            const float* __restrict__ w,
                            const float* __restrict__ nb,
                            float* __restrict__ film) {
    int b = blockIdx.x;
    int co = threadIdx.x;
    __shared__ float e[NC];
    e[co] = emb[b*NC + co];
    __syncthreads();
    float acc = nb[co];
    #pragma unroll 8
    for (int k = 0; k < NC; k++) acc += e[k] * w[k*NC + co];
    film[b*NC + co] = acc;
}

// ---------------- Fused single-pass GroupNorm (+optional SiLU) --------------
// One block per (b,g); slab of 8192 floats held in registers between the
// reduction and the normalization. Output tf32-rounded (feeds GEMMs only).
__global__ void gn_fused_kernel(const float* __restrict__ x,
                                const float* __restrict__ scale,
                                const float* __restrict__ bias,
                                float* __restrict__ y,
                                int do_silu) {
    int bg = blockIdx.x;                       // b*NG + g
    const float* p = x + (long)bg * 8192;
    float* q = y + (long)bg * 8192;
    int t = threadIdx.x;
    float v[32];
    float s = 0.f, s2 = 0.f;
    #pragma unroll
    for (int j = 0; j < 32; j++) {
        v[j] = p[t + j*256];
        s += v[j]; s2 += v[j]*v[j];
    }
    __shared__ float sh[256], sh2[256];
    sh[t] = s; sh2[t] = s2;
    __syncthreads();
    for (int o = 128; o > 0; o >>= 1) {
        if (t < o) { sh[t] += sh[t+o]; sh2[t] += sh2[t+o]; }
        __syncthreads();
    }
    float m = sh[0] * (1.f/8192.f);
    float var = sh2[0] * (1.f/8192.f) - m*m;
    float rstd = rsqrtf(var + 1e-5f);
    int cbase = (bg & (NG-1)) * 8;             // channels g*8 .. g*8+7
    #pragma unroll
    for (int j = 0; j < 32; j++) {
        int c = cbase + (j >> 2);              // (t + j*256) >> 10 == j >> 2
        float val = (v[j] - m) * rstd * scale[c] + bias[c];
        if (do_silu) val = val / (1.f + expf(-val));
        q[t + j*256] = to_tf32f(val);
    }
}

// ---------------- Softmax over rows of 1024 (float4), tf32-rounded ----------
__global__ void softmax_kernel(float* __restrict__ S) {
    long row = blockIdx.x;
    float4* p = reinterpret_cast<float4*>(S + row * NHW);
    int t = threadIdx.x;
    float4 v = p[t];
    float mx = fmaxf(fmaxf(v.x, v.y), fmaxf(v.z, v.w));
    __shared__ float sh[256];
    sh[t] = mx; __syncthreads();
    for (int o = 128; o > 0; o >>= 1) { if (t < o) sh[t] = fmaxf(sh[t], sh[t+o]); __syncthreads(); }
    mx = sh[0]; __syncthreads();
    v.x = expf(v.x - mx); v.y = expf(v.y - mx);
    v.z = expf(v.z - mx); v.w = expf(v.w - mx);
    sh[t] = v.x + v.y + v.z + v.w; __syncthreads();
    for (int o = 128; o > 0; o >>= 1) { if (t < o) sh[t] += sh[t+o]; __syncthreads(); }
    float inv = 1.f / sh[0];
    v.x = to_tf32f(v.x * inv); v.y = to_tf32f(v.y * inv);
    v.z = to_tf32f(v.z * inv); v.w = to_tf32f(v.w * inv);
    p[t] = v;
}

__device__ __forceinline__ void mma_tf32(float c[4], uint32_t a0, uint32_t a1,
                                         uint32_t a2, uint32_t a3,
                                         uint32_t b0, uint32_t b1) {
    asm volatile(
        "mma.sync.aligned.m16n8k8.row.col.f32.tf32.tf32.f32 "
        "{%0,%1,%2,%3}, {%4,%5,%6,%7}, {%8,%9}, {%0,%1,%2,%3};\n"
        : "+f"(c[0]), "+f"(c[1]), "+f"(c[2]), "+f"(c[3])
        : "r"(a0), "r"(a1), "r"(a2), "r"(a3), "r"(b0), "r"(b1));
}

// ---------------- Batched 256x128x16 TF32 GEMM, 3-stage cp.async ------------
// All inputs PRE-ROUNDED tf32 bits; 8 warps as 4m x 2n, 64x64 warp tiles.
// TA=0: A row-major [M][K], smem [m][k] stride 20
// TA=1: A is [K][M],        smem [k][m] stride 264
// TB=0: B is [K][N],        smem [k][n] stride 136
// TB=1: B is [N][K],        smem [n][k] stride 20
// IMC : B image [Ci][32][32], K=9*Ci with k=r*256+ci (tap-major); [k][n] 136.
#define SA0 20
#define SAM 264
#define SKN 136
#define SNK 20
#define ASZ 5120            // max(256*20, 16*264)
#define BSZ 2560            // max(16*136, 128*20)
#define STG (ASZ+BSZ)       // floats per stage
#define GEMM_SMEM (3*STG*4) // 92160 bytes

template<int TA, int TB, bool IMC, int RND>
__global__ __launch_bounds__(256)
void gemm_tc_kernel(const float* __restrict__ A,
                    const float* __restrict__ Bp,
                    float* __restrict__ Cp,
                    int M, int N, int K,
                    long sA, long sB, long sC,
                    float alpha,
                    const float* __restrict__ bias,
                    const float* __restrict__ film,
                    const float* __restrict__ addsrc,
                    int accumulate) {
    extern __shared__ __align__(16) float smem[];

    int b  = blockIdx.z;
    const float* Ab = A  + (long)b * sA;
    const float* Bb = Bp + (long)b * sB;
    float*       Cb = Cp + (long)b * sC;
    int m0 = blockIdx.y * 256;
    int n0 = blockIdx.x * 128;
    int t    = threadIdx.x;
    int lane = t & 31;
    int wid  = t >> 5;
    int wm   = wid >> 1;         // warp m index (0..3) -> 64 rows
    int wn   = wid & 1;          // warp n index (0..1) -> 64 cols
    int grp  = lane >> 2;        // 0..7
    int qd   = lane & 3;         // 0..3

    uint32_t sb = (uint32_t)__cvta_generic_to_shared(&smem[0]);

    float acc[4][8][4];
    #pragma unroll
    for (int i = 0; i < 4; i++)
        #pragma unroll
        for (int j = 0; j < 8; j++)
            #pragma unroll
            for (int r = 0; r < 4; r++) acc[i][j][r] = 0.f;

    // im2col per-thread constants
    int ic_n  = t & 127;
    int ic_kr = t >> 7;                    // 0..1
    int ic_h  = (n0 + ic_n) >> 5;
    int ic_w  = (n0 + ic_n) & 31;

    auto prefA = [&](int kk, int s) {
        uint32_t ab = sb + (uint32_t)(s*STG)*4u;
        if (TA == 0) {
            #pragma unroll
            for (int r = 0; r < 4; r++) {       // 256x16 = 1024 float4
                int c = t + r*256;
                int m = c >> 2;
                int kq = (c & 3) << 2;
                cp16(ab + (uint32_t)(m*SA0 + kq)*4u,
                     Ab + (long)(m0+m)*K + kk + kq);
            }
        } else {
            #pragma unroll
            for (int r = 0; r < 4; r++) {       // 16x256 = 1024 float4
                int c = t + r*256;
                int k = c >> 6;
                int mq = (c & 63) << 2;
                cp16(ab + (uint32_t)(k*SAM + mq)*4u,
                     Ab + (long)(kk+k)*M + m0 + mq);
            }
        }
    };
    auto prefB = [&](int kk, int s) {
        uint32_t bbase = sb + (uint32_t)(s*STG + ASZ)*4u;
        if (IMC) {
            int r   = kk >> 8;            // constant tap for this tile
            int ci0 = (kk & 255) + ic_kr*8;
            int kh  = r / 3, kw = r - kh*3;
            int ih  = ic_h + kh - 1, iw = ic_w + kw - 1;
            bool ok = (ih >= 0 && ih < 32 && iw >= 0 && iw < 32);
            const float* src = ok ? (Bb + (long)ci0*NHW + ih*32 + iw) : Bb;
            int sz = ok ? 4 : 0;
            #pragma unroll
            for (int j = 0; j < 8; j++)
                cp4z(bbase + (uint32_t)((ic_kr*8 + j)*SKN + ic_n)*4u,
                     src + j*NHW, sz);
        } else if (TB == 0) {
            #pragma unroll
            for (int r = 0; r < 2; r++) {       // 16x128 = 512 float4
                int c = t + r*256;
                int k = c >> 5;
                int nq = (c & 31) << 2;
                cp16(bbase + (uint32_t)(k*SKN + nq)*4u,
                     Bb + (long)(kk+k)*N + n0 + nq);
            }
        } else {
            #pragma unroll
            for (int r = 0; r < 2; r++) {       // 128x16 = 512 float4
                int c = t + r*256;
                int n = c >> 2;
                int kq = (c & 3) << 2;
                cp16(bbase + (uint32_t)(n*SNK + kq)*4u,
                     Bb + (long)(n0+n)*K + kk + kq);
            }
        }
    };
    auto compute = [&](int s) {
        const uint32_t* AsU = reinterpret_cast<const uint32_t*>(&smem[s*STG]);
        const uint32_t* BsU = reinterpret_cast<const uint32_t*>(&smem[s*STG + ASZ]);
        #pragma unroll
        for (int ks = 0; ks < 16; ks += 8) {
            uint32_t af[4][4];
            #pragma unroll
            for (int mt = 0; mt < 4; mt++) {
                int mb = wm*64 + mt*16 + grp;
                if (TA == 0) {
                    af[mt][0] = AsU[mb*SA0 + ks + qd];
                    af[mt][1] = AsU[(mb+8)*SA0 + ks + qd];
                    af[mt][2] = AsU[mb*SA0 + ks + 4 + qd];
                    af[mt][3] = AsU[(mb+8)*SA0 + ks + 4 + qd];
                } else {
                    af[mt][0] = AsU[(ks+qd)*SAM + mb];
                    af[mt][1] = AsU[(ks+qd)*SAM + mb + 8];
                    af[mt][2] = AsU[(ks+4+qd)*SAM + mb];
                    af[mt][3] = AsU[(ks+4+qd)*SAM + mb + 8];
                }
            }
            uint32_t bf[8][2];
            #pragma unroll
            for (int nt = 0; nt < 8; nt++) {
                int nb = wn*64 + nt*8 + grp;
                if (TB == 1) {
                    bf[nt][0] = BsU[nb*SNK + ks + qd];
                    bf[nt][1] = BsU[nb*SNK + ks + 4 + qd];
                } else {
                    bf[nt][0] = BsU[(ks+qd)*SKN + nb];
                    bf[nt][1] = BsU[(ks+4+qd)*SKN + nb];
                }
            }
            #pragma unroll
            for (int mt = 0; mt < 4; mt++)
                #pragma unroll
                for (int nt = 0; nt < 8; nt++)
                    mma_tf32(acc[mt][nt], af[mt][0], af[mt][1], af[mt][2], af[mt][3],
                             bf[nt][0], bf[nt][1]);
        }
    };

    // ---- 3-stage pipelined mainloop ----
    int T = K >> 4;
    prefA(0, 0); prefB(0, 0); cp_commit();
    prefA(16, 1); prefB(16, 1); cp_commit();
    for (int i = 0; i < T; i++) {
        cp_wait1();
        __syncthreads();
        if (i + 2 < T) {
            int s2 = (i + 2) % 3;
            prefA((i+2)*16, s2); prefB((i+2)*16, s2);
        }
        cp_commit();
        compute(i % 3);
        __syncthreads();
    }

    // ---- epilogue ----
    #pragma unroll
    for (int mt = 0; mt < 4; mt++) {
        int mr0 = m0 + wm*64 + mt*16 + grp;
        int mr1 = mr0 + 8;
        float badd0 = 0.f, badd1 = 0.f;
        if (bias) { badd0 += bias[mr0]; badd1 += bias[mr1]; }
        if (film) { badd0 += film[b*M + mr0]; badd1 += film[b*M + mr1]; }
        #pragma unroll
        for (int nt = 0; nt < 8; nt++) {
            int nc = n0 + wn*64 + nt*8 + qd*2;
            long i0 = (long)mr0 * N + nc;
            long i1 = (long)mr1 * N + nc;
            float v00 = acc[mt][nt][0] * alpha + badd0;
            float v01 = acc[mt][nt][1] * alpha + badd0;
            float v10 = acc[mt][nt][2] * alpha + badd1;
            float v11 = acc[mt][nt][3] * alpha + badd1;
            if (addsrc) {
                v00 += addsrc[(long)b*sC + i0];
                v01 += addsrc[(long)b*sC + i0 + 1];
                v10 += addsrc[(long)b*sC + i1];
                v11 += addsrc[(long)b*sC + i1 + 1];
            }
            if (accumulate) {
                v00 += Cb[i0]; v01 += Cb[i0 + 1];
                v10 += Cb[i1]; v11 += Cb[i1 + 1];
            }
            if (RND) {
                v00 = to_tf32f(v00); v01 = to_tf32f(v01);
                v10 = to_tf32f(v10); v11 = to_tf32f(v11);
            }
            *reinterpret_cast<float2*>(&Cb[i0]) = make_float2(v00, v01);
            *reinterpret_cast<float2*>(&Cb[i1]) = make_float2(v10, v11);
        }
    }
}

// ---------------- host launch ------------------------------------------------
extern "C" void kernel_launch(void* const* d_in, const int* in_sizes, int n_in,
                              void* d_out, int out_size) {
    const float* x          = (const float*)d_in[0];
    const float* noise_emb  = (const float*)d_in[1];
    const float* gn1_scale  = (const float*)d_in[2];
    const float* gn1_bias   = (const float*)d_in[3];
    const float* conv1_w    = (const float*)d_in[4];
    const float* conv1_b    = (const float*)d_in[5];
    const float* noise_w    = (const float*)d_in[6];
    const float* noise_b    = (const float*)d_in[7];
    const float* gn2_scale  = (const float*)d_in[8];
    const float* gn2_bias   = (const float*)d_in[9];
    const float* conv2_w    = (const float*)d_in[10];
    const float* conv2_b    = (const float*)d_in[11];
    const float* res_w      = (const float*)d_in[12];
    const float* res_b      = (const float*)d_in[13];
    const float* agn_scale  = (const float*)d_in[14];
    const float* agn_bias   = (const float*)d_in[15];
    const float* qkv_w      = (const float*)d_in[16];
    const float* out_w      = (const float*)d_in[17];
    const float* out_b      = (const float*)d_in[18];
    float* out = (float*)d_out;

    float *t0, *t1, *t2, *h, *qkv, *att, *film;
    float *pw1, *pw2, *wq, *wr, *wo, *xc;
    cudaGetSymbolAddress((void**)&t0,   g_t0);
    cudaGetSymbolAddress((void**)&t1,   g_t1);
    cudaGetSymbolAddress((void**)&t2,   g_t2);
    cudaGetSymbolAddress((void**)&h,    g_h);
    cudaGetSymbolAddress((void**)&qkv,  g_qkv);
    cudaGetSymbolAddress((void**)&att,  g_att);
    cudaGetSymbolAddress((void**)&film, g_film);
    cudaGetSymbolAddress((void**)&pw1,  g_pw1);
    cudaGetSymbolAddress((void**)&pw2,  g_pw2);
    cudaGetSymbolAddress((void**)&wq,   g_wq);
    cudaGetSymbolAddress((void**)&wr,   g_wr);
    cudaGetSymbolAddress((void**)&wo,   g_wo);
    cudaGetSymbolAddress((void**)&xc,   g_xc);

    cudaFuncSetAttribute(gemm_tc_kernel<0,0,true,0>,
        cudaFuncAttributeMaxDynamicSharedMemorySize, GEMM_SMEM);
    cudaFuncSetAttribute(gemm_tc_kernel<0,0,false,0>,
        cudaFuncAttributeMaxDynamicSharedMemorySize, GEMM_SMEM);
    cudaFuncSetAttribute(gemm_tc_kernel<0,0,false,1>,
        cudaFuncAttributeMaxDynamicSharedMemorySize, GEMM_SMEM);
    cudaFuncSetAttribute(gemm_tc_kernel<1,0,false,0>,
        cudaFuncAttributeMaxDynamicSharedMemorySize, GEMM_SMEM);
    cudaFuncSetAttribute(gemm_tc_kernel<0,1,false,1>,
        cudaFuncAttributeMaxDynamicSharedMemorySize, GEMM_SMEM);

    const int ELTS = NB * CHW;            // 4194304
    const int EW_GRID = ELTS / 256;       // 16384
    const int PW_GRID = NC*KC/256;        // 2304

    // ncu empirically captures launch #4 -> conv1 GEMM goes there.
    film_kernel<<<NB, NC>>>(noise_emb, noise_w, noise_b, film);              // 1
    permw_kernel<<<PW_GRID, 256>>>(conv1_w, pw1);                            // 2
    gn_fused_kernel<<<NB*NG, 256>>>(x, gn1_scale, gn1_bias, t0, 1);          // 3

    // conv1 (3x3, tap-major im2col GEMM) + FiLM add fused                   // 4
    gemm_tc_kernel<0,0,true,0><<<dim3(8,1,NB), 256, GEMM_SMEM>>>(
        pw1, t0, t1, NC, NHW, KC, 0, CHW, CHW, 1.f,
        conv1_b, film, nullptr, 0);

    // remaining one-shot conversions
    permw_kernel<<<PW_GRID, 256>>>(conv2_w, pw2);
    cvt_kernel<<<3*NC*NC/256, 256>>>(qkv_w, wq);
    cvt_kernel<<<NC*NC/256, 256>>>(res_w, wr);
    cvt_kernel<<<NC*NC/256, 256>>>(out_w, wo);
    cvt_kernel<<<EW_GRID, 256>>>(x, xc);

    // GN2 + SiLU (fused, tf32 out)
    gn_fused_kernel<<<NB*NG, 256>>>(t1, gn2_scale, gn2_bias, t2, 1);

    // residual 1x1 conv -> h (fp32 out)
    gemm_tc_kernel<0,0,false,0><<<dim3(8,1,NB), 256, GEMM_SMEM>>>(
        wr, xc, h, NC, NHW, NC, 0, CHW, CHW, 1.f,
        res_b, nullptr, nullptr, 0);

    // conv2 (3x3) accumulates into h (fp32)
    gemm_tc_kernel<0,0,true,0><<<dim3(8,1,NB), 256, GEMM_SMEM>>>(
        pw2, t2, h, NC, NHW, KC, 0, CHW, CHW, 1.f,
        conv2_b, nullptr, nullptr, 1);

    // attention GroupNorm (fused, no SiLU, tf32 out) -> t0
    gn_fused_kernel<<<NB*NG, 256>>>(h, agn_scale, agn_bias, t0, 0);

    // qkv 1x1 conv (no bias), output tf32-rounded
    gemm_tc_kernel<0,0,false,1><<<dim3(8,3,NB), 256, GEMM_SMEM>>>(
        wq, t0, qkv, 3*NC, NHW, NC, 0, CHW, (long)3*CHW, 1.f,
        nullptr, nullptr, nullptr, 0);

    // scores: S[b][s][t] = (1/16) * sum_d q[d][s] k[d][t]   (A is [K][M])
    gemm_tc_kernel<1,0,false,0><<<dim3(8,4,NB), 256, GEMM_SMEM>>>(
        qkv /*q*/, qkv + CHW /*k*/, att, NHW, NHW, NC,
        (long)3*CHW, (long)3*CHW, (long)NHW*NHW, 0.0625f,
        nullptr, nullptr, nullptr, 0);

    // softmax rows (float4, tf32 out)
    softmax_kernel<<<NB*NHW, 256>>>(att);

    // AV: O[b][d][s] = sum_t v[d][t] S[s][t] (B is [N][K]) -> t2
    gemm_tc_kernel<0,1,false,1><<<dim3(8,1,NB), 256, GEMM_SMEM>>>(
        qkv + 2*CHW /*v*/, att, t2, NC, NHW, NHW,
        (long)3*CHW, (long)NHW*NHW, CHW, 1.f,
        nullptr, nullptr, nullptr, 0);

    // out 1x1 conv + bias + residual h -> d_out (fp32)
    gemm_tc_kernel<0,0,false,0><<<dim3(8,1,NB), 256, GEMM_SMEM>>>(
        wo, t2, out, NC, NHW, NC, 0, CHW, CHW, 1.f,
        out_b, nullptr, h, 0);
}